// round 2
// baseline (speedup 1.0000x reference)
#include <cuda_runtime.h>
#include <math.h>

#define CH   128
#define HH   64
#define WW   128
#define DD   32
#define NV   2

#define TWO_PI_F 6.2831853071795864769f
#define PI_F     3.1415926535897932385f

// channel-last transposed features: featT[v][h][w][c], stored as float4 (c/4)
__device__ float4 g_featT[NV * HH * WW * (CH / 4)];   // 8 MB
__device__ float  g_pose[2][12];                      // row-major 3x4 [R|t]
__device__ float  g_depth[2][DD];

// ---------------------------------------------------------------------------
// Setup: analytic rigid inverse for pose = inv(E1) @ E0 and its inverse,
// plus inverse-depth candidate table.
// ---------------------------------------------------------------------------
__global__ void setup_kernel(const float* __restrict__ ex,
                             const float* __restrict__ nearp,
                             const float* __restrict__ farp) {
    int t = threadIdx.x;
    if (t == 0) {
        float R0[3][3], R1[3][3], t0[3], t1[3];
        #pragma unroll
        for (int i = 0; i < 3; ++i) {
            #pragma unroll
            for (int j = 0; j < 3; ++j) {
                R0[i][j] = ex[i * 4 + j];
                R1[i][j] = ex[16 + i * 4 + j];
            }
            t0[i] = ex[i * 4 + 3];
            t1[i] = ex[16 + i * 4 + 3];
        }
        // pose (n=0): Rp = R1^T R0 ; tp = R1^T (t0 - t1)
        float Rp[3][3], tp[3];
        #pragma unroll
        for (int i = 0; i < 3; ++i) {
            #pragma unroll
            for (int j = 0; j < 3; ++j)
                Rp[i][j] = R1[0][i] * R0[0][j] + R1[1][i] * R0[1][j] + R1[2][i] * R0[2][j];
            tp[i] = R1[0][i] * (t0[0] - t1[0]) + R1[1][i] * (t0[1] - t1[1])
                  + R1[2][i] * (t0[2] - t1[2]);
        }
        #pragma unroll
        for (int i = 0; i < 3; ++i) {
            #pragma unroll
            for (int j = 0; j < 3; ++j) {
                g_pose[0][i * 4 + j] = Rp[i][j];
                g_pose[1][i * 4 + j] = Rp[j][i];          // inverse rotation
            }
            g_pose[0][i * 4 + 3] = tp[i];
            g_pose[1][i * 4 + 3] = -(Rp[0][i] * tp[0] + Rp[1][i] * tp[1] + Rp[2][i] * tp[2]);
        }
    }
    if (t < 2 * DD) {
        int n = t >> 5;
        int d = t & (DD - 1);
        float mind = 1.0f / farp[n];
        float maxd = 1.0f / nearp[n];
        float lin  = (float)d * (1.0f / (float)(DD - 1));
        g_depth[n][d] = 1.0f / (mind + lin * (maxd - mind));
    }
}

// ---------------------------------------------------------------------------
// Transpose (v,c,h,w) -> (v,h,w,c) via 32x32 smem tiles (conflict-free).
// grid: (W/32, C/32, V*H), block (32, 8)
// ---------------------------------------------------------------------------
__global__ void transpose_kernel(const float* __restrict__ feat) {
    __shared__ float tile[32][33];
    int v  = blockIdx.z >> 6;
    int h  = blockIdx.z & 63;
    int w0 = blockIdx.x << 5;
    int c0 = blockIdx.y << 5;
    int tx = threadIdx.x, ty = threadIdx.y;

    #pragma unroll
    for (int i = 0; i < 32; i += 8)
        tile[ty + i][tx] = feat[(((v * CH) + (c0 + ty + i)) * HH + h) * WW + (w0 + tx)];
    __syncthreads();

    float* fT = reinterpret_cast<float*>(g_featT);
    #pragma unroll
    for (int i = 0; i < 32; i += 8)
        fT[(((v * HH + h) * WW) + (w0 + ty + i)) * CH + (c0 + tx)] = tile[tx][ty + i];
}

// ---------------------------------------------------------------------------
// Main: 1 block per (n,h,w), 8 warps x 4 depths each.
// Per depth: spherical warp -> 4 coalesced float4 tap columns -> dot -> reduce.
// ---------------------------------------------------------------------------
__global__ void __launch_bounds__(256) corr_kernel(float* __restrict__ out) {
    int bid = blockIdx.x;
    int w = bid & (WW - 1);
    int h = (bid >> 7) & (HH - 1);
    int n = bid >> 13;

    __shared__ float4 s_f0[CH / 4];
    __shared__ float  s_pose[12];

    int tid = threadIdx.x;
    if (tid < 12) s_pose[tid] = g_pose[n][tid];
    if (tid < CH / 4)
        s_f0[tid] = g_featT[(((n * HH + h) * WW + w) * (CH / 4)) + tid];
    __syncthreads();

    int lane = tid & 31;
    int wid  = tid >> 5;

    float theta = ((float)w + 0.5f) * (TWO_PI_F / (float)WW);
    float phi   = ((float)h + 0.5f) * (PI_F / (float)HH);
    float sth, cth, sphi, cphi;
    sincosf(theta, &sth, &cth);
    sincosf(phi, &sphi, &cphi);
    float dx = sphi * sth;
    float dy = cphi;
    float dz = sphi * cth;

    float p0 = s_pose[0], p1 = s_pose[1], p2 = s_pose[2],  p3 = s_pose[3];
    float p4 = s_pose[4], p5 = s_pose[5], p6 = s_pose[6],  p7 = s_pose[7];
    float p8 = s_pose[8], p9 = s_pose[9], pa = s_pose[10], pb = s_pose[11];

    float4 f0 = s_f0[lane];
    int vv = 1 - n;
    const float4* __restrict__ base = g_featT + ((size_t)vv * HH * WW * (CH / 4));

    #pragma unroll
    for (int k = 0; k < 4; ++k) {
        int d = (wid << 2) + k;
        float dep = g_depth[n][d];
        float px = dep * dx, py = dep * dy, pz = dep * dz;

        float X = p0 * px + p1 * py + p2 * pz + p3;
        float Y = p4 * px + p5 * py + p6 * pz + p7;
        float Z = p8 * px + p9 * py + pa * pz + pb;

        float r = sqrtf(X * X + Y * Y + Z * Z);
        r = fmaxf(r, 0.001f);
        float cph = fminf(fmaxf(Y / r, -1.0f), 1.0f);
        float phw = acosf(cph);
        float thw = fmodf(atan2f(X, Z), TWO_PI_F);
        if (thw < 0.0f) thw += TWO_PI_F;

        float u  = thw * (2.0f / TWO_PI_F) - 1.0f;
        float v_ = phw * (2.0f / PI_F) - 1.0f;
        float ix = (u  + 1.0f) * 0.5f * (float)(WW - 1);
        float iy = (v_ + 1.0f) * 0.5f * (float)(HH - 1);

        float x0f = floorf(ix), y0f = floorf(iy);
        float x1f = x0f + 1.0f, y1f = y0f + 1.0f;
        float wx1 = ix - x0f, wy1 = iy - y0f;
        float wx0 = 1.0f - wx1, wy0 = 1.0f - wy1;

        float vx0 = (x0f >= 0.0f && x0f <= (float)(WW - 1)) ? 1.0f : 0.0f;
        float vx1 = (x1f >= 0.0f && x1f <= (float)(WW - 1)) ? 1.0f : 0.0f;
        float vy0 = (y0f >= 0.0f && y0f <= (float)(HH - 1)) ? 1.0f : 0.0f;
        float vy1 = (y1f >= 0.0f && y1f <= (float)(HH - 1)) ? 1.0f : 0.0f;

        int x0 = min(max((int)x0f, 0), WW - 1);
        int x1 = min(max((int)x1f, 0), WW - 1);
        int y0 = min(max((int)y0f, 0), HH - 1);
        int y1 = min(max((int)y1f, 0), HH - 1);

        int r0 = y0 << 12;   // y * W * (C/4) = y*4096
        int r1 = y1 << 12;
        float4 t00 = base[r0 + (x0 << 5) + lane];
        float4 t10 = base[r0 + (x1 << 5) + lane];
        float4 t01 = base[r1 + (x0 << 5) + lane];
        float4 t11 = base[r1 + (x1 << 5) + lane];

        float a00 = f0.x * t00.x + f0.y * t00.y + f0.z * t00.z + f0.w * t00.w;
        float a10 = f0.x * t10.x + f0.y * t10.y + f0.z * t10.z + f0.w * t10.w;
        float a01 = f0.x * t01.x + f0.y * t01.y + f0.z * t01.z + f0.w * t01.w;
        float a11 = f0.x * t11.x + f0.y * t11.y + f0.z * t11.z + f0.w * t11.w;

        float acc = (wx0 * wy0 * vx0 * vy0) * a00
                  + (wx1 * wy0 * vx1 * vy0) * a10
                  + (wx0 * wy1 * vx0 * vy1) * a01
                  + (wx1 * wy1 * vx1 * vy1) * a11;

        #pragma unroll
        for (int off = 16; off; off >>= 1)
            acc += __shfl_xor_sync(0xffffffffu, acc, off);

        if (lane == 0)
            out[(((n * DD + d) * HH + h) << 7) + w] = acc * 0.08838834764831844f; // 1/sqrt(128)
    }
}

extern "C" void kernel_launch(void* const* d_in, const int* in_sizes, int n_in,
                              void* d_out, int out_size) {
    const float* features = (const float*)d_in[0];
    const float* extr     = (const float*)d_in[1];
    const float* nearp    = (const float*)d_in[2];
    const float* farp     = (const float*)d_in[3];
    float* out = (float*)d_out;

    setup_kernel<<<1, 64>>>(extr, nearp, farp);
    transpose_kernel<<<dim3(WW / 32, CH / 32, NV * HH), dim3(32, 8)>>>(features);
    corr_kernel<<<NV * HH * WW, 256>>>(out);
}

// round 3
// speedup vs baseline: 2.2643x; 2.2643x over previous
#include <cuda_runtime.h>
#include <cuda_fp16.h>
#include <math.h>

#define CH   128
#define HH   64
#define WW   128
#define DD   32
#define NV   2

#define TWO_PI_F 6.2831853071795864769f
#define PI_F     3.1415926535897932385f

// channel-last copies: fp32 for feat0 (smem dot operand), fp16 for gathered taps
__device__ float4 g_featT[NV * HH * WW * (CH / 4)];   // 8 MB
__device__ __half g_featH[NV * HH * WW * CH];         // 4 MB
__device__ float  g_pose[2][12];
__device__ float  g_depth[2][DD];

// ---------------------------------------------------------------------------
__global__ void setup_kernel(const float* __restrict__ ex,
                             const float* __restrict__ nearp,
                             const float* __restrict__ farp) {
    int t = threadIdx.x;
    if (t == 0) {
        float R0[3][3], R1[3][3], t0[3], t1[3];
        #pragma unroll
        for (int i = 0; i < 3; ++i) {
            #pragma unroll
            for (int j = 0; j < 3; ++j) {
                R0[i][j] = ex[i * 4 + j];
                R1[i][j] = ex[16 + i * 4 + j];
            }
            t0[i] = ex[i * 4 + 3];
            t1[i] = ex[16 + i * 4 + 3];
        }
        float Rp[3][3], tp[3];
        #pragma unroll
        for (int i = 0; i < 3; ++i) {
            #pragma unroll
            for (int j = 0; j < 3; ++j)
                Rp[i][j] = R1[0][i] * R0[0][j] + R1[1][i] * R0[1][j] + R1[2][i] * R0[2][j];
            tp[i] = R1[0][i] * (t0[0] - t1[0]) + R1[1][i] * (t0[1] - t1[1])
                  + R1[2][i] * (t0[2] - t1[2]);
        }
        #pragma unroll
        for (int i = 0; i < 3; ++i) {
            #pragma unroll
            for (int j = 0; j < 3; ++j) {
                g_pose[0][i * 4 + j] = Rp[i][j];
                g_pose[1][i * 4 + j] = Rp[j][i];
            }
            g_pose[0][i * 4 + 3] = tp[i];
            g_pose[1][i * 4 + 3] = -(Rp[0][i] * tp[0] + Rp[1][i] * tp[1] + Rp[2][i] * tp[2]);
        }
    }
    if (t < 2 * DD) {
        int n = t >> 5;
        int d = t & (DD - 1);
        float mind = 1.0f / farp[n];
        float maxd = 1.0f / nearp[n];
        float lin  = (float)d * (1.0f / (float)(DD - 1));
        g_depth[n][d] = 1.0f / (mind + lin * (maxd - mind));
    }
}

// ---------------------------------------------------------------------------
// Transpose (v,c,h,w) -> (v,h,w,c), writing fp32 and fp16 copies.
// grid: (W/32, C/32, V*H), block (32, 8)
// ---------------------------------------------------------------------------
__global__ void transpose_kernel(const float* __restrict__ feat) {
    __shared__ float tile[32][33];
    int v  = blockIdx.z >> 6;
    int h  = blockIdx.z & 63;
    int w0 = blockIdx.x << 5;
    int c0 = blockIdx.y << 5;
    int tx = threadIdx.x, ty = threadIdx.y;

    #pragma unroll
    for (int i = 0; i < 32; i += 8)
        tile[ty + i][tx] = feat[(((v * CH) + (c0 + ty + i)) * HH + h) * WW + (w0 + tx)];
    __syncthreads();

    float* fT = reinterpret_cast<float*>(g_featT);
    #pragma unroll
    for (int i = 0; i < 32; i += 8) {
        float val = tile[tx][ty + i];
        size_t idx = (size_t)(((v * HH + h) * WW) + (w0 + ty + i)) * CH + (c0 + tx);
        fT[idx] = val;
        g_featH[idx] = __float2half_rn(val);
    }
}

// ---------------------------------------------------------------------------
// Main: block = (n, h, 8 adjacent w). 8 warps, 1 warp per pixel, 32 depths.
// Phase 1: lane d computes projection for depth d (packed coords + 4 weights).
// Phase 2: loop depths; broadcast; 4 fp16 tap columns; dot vs fp32 feat0; reduce.
// ---------------------------------------------------------------------------
__global__ void __launch_bounds__(256) corr_kernel(float* __restrict__ out) {
    int bid = blockIdx.x;                 // 2048 blocks
    int wt = bid & 15;                    // 16 tiles of 8 pixels
    int h  = (bid >> 4) & (HH - 1);
    int n  = bid >> 10;

    __shared__ float4 s_f0[8][32];
    __shared__ float  s_pose[12];
    __shared__ float  s_depth[DD];

    int tid  = threadIdx.x;
    int lane = tid & 31;
    int wid  = tid >> 5;

    if (tid < 12) s_pose[tid] = g_pose[n][tid];
    if (tid >= 32 && tid < 64) s_depth[tid - 32] = g_depth[n][tid - 32];
    s_f0[wid][lane] = g_featT[(size_t)(((n * HH + h) * WW) + (wt * 8 + wid)) * 32 + lane];
    __syncthreads();

    int w = wt * 8 + wid;

    // ---- phase 1: per-lane projection for depth = lane ----
    float theta = ((float)w + 0.5f) * (TWO_PI_F / (float)WW);
    float phi   = ((float)h + 0.5f) * (PI_F / (float)HH);
    float sth, cth, sphi, cphi;
    sincosf(theta, &sth, &cth);
    sincosf(phi, &sphi, &cphi);
    float dep = s_depth[lane];
    float px = dep * sphi * sth;
    float py = dep * cphi;
    float pz = dep * sphi * cth;

    float X = s_pose[0] * px + s_pose[1] * py + s_pose[2]  * pz + s_pose[3];
    float Y = s_pose[4] * px + s_pose[5] * py + s_pose[6]  * pz + s_pose[7];
    float Z = s_pose[8] * px + s_pose[9] * py + s_pose[10] * pz + s_pose[11];

    float r = fmaxf(sqrtf(X * X + Y * Y + Z * Z), 0.001f);
    float cph = fminf(fmaxf(Y / r, -1.0f), 1.0f);
    float phw = acosf(cph);
    float thw = atan2f(X, Z);
    if (thw < 0.0f) thw += TWO_PI_F;

    float ix = (thw * (1.0f / TWO_PI_F)) * (float)(WW - 1) * 2.0f * 0.5f;  // == thw/2pi*(W-1)
    float iy = (phw * (1.0f / PI_F)) * (float)(HH - 1);

    float x0f = floorf(ix), y0f = floorf(iy);
    float x1f = x0f + 1.0f, y1f = y0f + 1.0f;
    float wx1 = ix - x0f, wy1 = iy - y0f;
    float wx0 = 1.0f - wx1, wy0 = 1.0f - wy1;

    // fold validity masks into weights
    if (!(x0f >= 0.0f && x0f <= (float)(WW - 1))) wx0 = 0.0f;
    if (!(x1f >= 0.0f && x1f <= (float)(WW - 1))) wx1 = 0.0f;
    if (!(y0f >= 0.0f && y0f <= (float)(HH - 1))) wy0 = 0.0f;
    if (!(y1f >= 0.0f && y1f <= (float)(HH - 1))) wy1 = 0.0f;

    float w00 = wx0 * wy0, w10 = wx1 * wy0, w01 = wx0 * wy1, w11 = wx1 * wy1;

    int x0 = min(max((int)x0f, 0), WW - 1);
    int x1 = min(max((int)x1f, 0), WW - 1);
    int y0 = min(max((int)y0f, 0), HH - 1);
    int y1 = min(max((int)y1f, 0), HH - 1);
    int packed = x0 | (x1 << 7) | (y0 << 14) | (y1 << 20);

    // ---- phase 2: loop depths, broadcast, gather, dot, reduce ----
    float4 f0 = s_f0[wid][lane];
    int vv = 1 - n;
    const float2* __restrict__ base =
        reinterpret_cast<const float2*>(g_featH) + (size_t)vv * HH * WW * 32;

    int out_base = (((n * DD) * HH + h) << 7) + w;

    #pragma unroll 4
    for (int d = 0; d < DD; ++d) {
        int   pk  = __shfl_sync(0xffffffffu, packed, d);
        float b00 = __shfl_sync(0xffffffffu, w00, d);
        float b10 = __shfl_sync(0xffffffffu, w10, d);
        float b01 = __shfl_sync(0xffffffffu, w01, d);
        float b11 = __shfl_sync(0xffffffffu, w11, d);

        int bx0 = pk & 127;
        int bx1 = (pk >> 7) & 127;
        int by0 = (pk >> 14) & 63;
        int by1 = (pk >> 20) & 63;

        int r0 = by0 << 7, r1 = by1 << 7;
        float2 v00 = base[((r0 + bx0) << 5) + lane];
        float2 v10 = base[((r0 + bx1) << 5) + lane];
        float2 v01 = base[((r1 + bx0) << 5) + lane];
        float2 v11 = base[((r1 + bx1) << 5) + lane];

        float2 a0 = __half22float2(*reinterpret_cast<const __half2*>(&v00.x));
        float2 a1 = __half22float2(*reinterpret_cast<const __half2*>(&v00.y));
        float acc = b00 * (f0.x * a0.x + f0.y * a0.y + f0.z * a1.x + f0.w * a1.y);

        a0 = __half22float2(*reinterpret_cast<const __half2*>(&v10.x));
        a1 = __half22float2(*reinterpret_cast<const __half2*>(&v10.y));
        acc += b10 * (f0.x * a0.x + f0.y * a0.y + f0.z * a1.x + f0.w * a1.y);

        a0 = __half22float2(*reinterpret_cast<const __half2*>(&v01.x));
        a1 = __half22float2(*reinterpret_cast<const __half2*>(&v01.y));
        acc += b01 * (f0.x * a0.x + f0.y * a0.y + f0.z * a1.x + f0.w * a1.y);

        a0 = __half22float2(*reinterpret_cast<const __half2*>(&v11.x));
        a1 = __half22float2(*reinterpret_cast<const __half2*>(&v11.y));
        acc += b11 * (f0.x * a0.x + f0.y * a0.y + f0.z * a1.x + f0.w * a1.y);

        #pragma unroll
        for (int off = 16; off; off >>= 1)
            acc += __shfl_xor_sync(0xffffffffu, acc, off);

        if (lane == 0)
            out[out_base + ((d * HH) << 7)] = acc * 0.08838834764831844f; // 1/sqrt(128)
    }
}

extern "C" void kernel_launch(void* const* d_in, const int* in_sizes, int n_in,
                              void* d_out, int out_size) {
    const float* features = (const float*)d_in[0];
    const float* extr     = (const float*)d_in[1];
    const float* nearp    = (const float*)d_in[2];
    const float* farp     = (const float*)d_in[3];
    float* out = (float*)d_out;

    setup_kernel<<<1, 64>>>(extr, nearp, farp);
    transpose_kernel<<<dim3(WW / 32, CH / 32, NV * HH), dim3(32, 8)>>>(features);
    corr_kernel<<<NV * HH * (WW / 8), 256>>>(out);
}

// round 4
// speedup vs baseline: 2.3719x; 1.0475x over previous
#include <cuda_runtime.h>
#include <cuda_fp16.h>
#include <math.h>

#define CH   128
#define HH   64
#define WW   128
#define DD   32
#define NV   2

#define TWO_PI_F 6.2831853071795864769f
#define PI_F     3.1415926535897932385f

// channel-last copies: fp32 for feat0 dot operand, fp16 for gathered taps.
// g_featH has one extra zeroed 256B column of padding for the x0==127 corner.
__device__ float4 g_featT[NV * HH * WW * (CH / 4)];        // 8 MB
__device__ __half g_featH[NV * HH * WW * CH + 2 * CH];     // 4 MB + pad
__device__ float  g_pose[2][12];
__device__ float  g_depth[2][DD];

// ---------------------------------------------------------------------------
// Transpose (v,c,h,w) -> (v,h,w,c), fp32 + fp16 copies. Block (0,0,0) thread 0
// additionally computes pose/depth tables (setup merged to save a launch).
// grid: (W/32, C/32, V*H), block (32, 8)
// ---------------------------------------------------------------------------
__global__ void transpose_kernel(const float* __restrict__ feat,
                                 const float* __restrict__ ex,
                                 const float* __restrict__ nearp,
                                 const float* __restrict__ farp) {
    __shared__ float tile[32][33];
    int v  = blockIdx.z >> 6;
    int h  = blockIdx.z & 63;
    int w0 = blockIdx.x << 5;
    int c0 = blockIdx.y << 5;
    int tx = threadIdx.x, ty = threadIdx.y;
    int lt = ty * 32 + tx;

    if (blockIdx.x == 0 && blockIdx.y == 0 && blockIdx.z == 0) {
        if (lt == 0) {
            float R0[3][3], R1[3][3], t0[3], t1[3];
            #pragma unroll
            for (int i = 0; i < 3; ++i) {
                #pragma unroll
                for (int j = 0; j < 3; ++j) {
                    R0[i][j] = ex[i * 4 + j];
                    R1[i][j] = ex[16 + i * 4 + j];
                }
                t0[i] = ex[i * 4 + 3];
                t1[i] = ex[16 + i * 4 + 3];
            }
            float Rp[3][3], tp[3];
            #pragma unroll
            for (int i = 0; i < 3; ++i) {
                #pragma unroll
                for (int j = 0; j < 3; ++j)
                    Rp[i][j] = R1[0][i] * R0[0][j] + R1[1][i] * R0[1][j] + R1[2][i] * R0[2][j];
                tp[i] = R1[0][i] * (t0[0] - t1[0]) + R1[1][i] * (t0[1] - t1[1])
                      + R1[2][i] * (t0[2] - t1[2]);
            }
            #pragma unroll
            for (int i = 0; i < 3; ++i) {
                #pragma unroll
                for (int j = 0; j < 3; ++j) {
                    g_pose[0][i * 4 + j] = Rp[i][j];
                    g_pose[1][i * 4 + j] = Rp[j][i];
                }
                g_pose[0][i * 4 + 3] = tp[i];
                g_pose[1][i * 4 + 3] = -(Rp[0][i] * tp[0] + Rp[1][i] * tp[1] + Rp[2][i] * tp[2]);
            }
        }
        if (lt >= 64 && lt < 64 + 2 * DD) {
            int t = lt - 64;
            int n = t >> 5;
            int d = t & (DD - 1);
            float mind = 1.0f / farp[n];
            float maxd = 1.0f / nearp[n];
            float lin  = (float)d * (1.0f / (float)(DD - 1));
            g_depth[n][d] = 1.0f / (mind + lin * (maxd - mind));
        }
    }

    #pragma unroll
    for (int i = 0; i < 32; i += 8)
        tile[ty + i][tx] = feat[(((v * CH) + (c0 + ty + i)) * HH + h) * WW + (w0 + tx)];
    __syncthreads();

    float* fT = reinterpret_cast<float*>(g_featT);
    #pragma unroll
    for (int i = 0; i < 32; i += 8) {
        float val = tile[tx][ty + i];
        size_t idx = (size_t)(((v * HH + h) * WW) + (w0 + ty + i)) * CH + (c0 + tx);
        fT[idx] = val;
        g_featH[idx] = __float2half_rn(val);
    }
}

// ---------------------------------------------------------------------------
// Main: block = (n, h, 16 adjacent w). 16 warps, 1 warp per pixel, 32 depths.
// Phase 1: lane d projects depth d -> packed coords + 4 bilinear weights.
// Phase 2: per depth, 2 x LDG.128 spans (row y0, row y1), each span covering
//          columns x0 and x0+1 (lanes 0-15 / 16-31), fp16->fp32 dot, reduce.
// ---------------------------------------------------------------------------
__global__ void __launch_bounds__(512, 2) corr_kernel(float* __restrict__ out) {
    int bid = blockIdx.x;                 // 1024 blocks
    int wt = bid & 7;                     // 8 tiles of 16 pixels
    int h  = (bid >> 3) & (HH - 1);
    int n  = bid >> 9;

    __shared__ float s_pose[12];
    __shared__ float s_depth[DD];

    int tid  = threadIdx.x;
    int lane = tid & 31;
    int wid  = tid >> 5;

    if (tid < 12) s_pose[tid] = g_pose[n][tid];
    if (tid >= 32 && tid < 64) s_depth[tid - 32] = g_depth[n][tid - 32];
    __syncthreads();

    int w = wt * 16 + wid;
    int halfsel = lane >> 4;              // 0: x0 column, 1: x1 column

    // f0 channels for this lane: 8*(lane&15) .. +7 (fp32)
    const float4* f0col = g_featT + (size_t)(((n * HH + h) * WW) + w) * 32;
    float4 f0a = f0col[(lane & 15) * 2];
    float4 f0b = f0col[(lane & 15) * 2 + 1];

    // ---- phase 1: per-lane projection for depth = lane ----
    float theta = ((float)w + 0.5f) * (TWO_PI_F / (float)WW);
    float phi   = ((float)h + 0.5f) * (PI_F / (float)HH);
    float sth, cth, sphi, cphi;
    sincosf(theta, &sth, &cth);
    sincosf(phi, &sphi, &cphi);
    float dep = s_depth[lane];
    float px = dep * sphi * sth;
    float py = dep * cphi;
    float pz = dep * sphi * cth;

    float X = s_pose[0] * px + s_pose[1] * py + s_pose[2]  * pz + s_pose[3];
    float Y = s_pose[4] * px + s_pose[5] * py + s_pose[6]  * pz + s_pose[7];
    float Z = s_pose[8] * px + s_pose[9] * py + s_pose[10] * pz + s_pose[11];

    float r = fmaxf(sqrtf(X * X + Y * Y + Z * Z), 0.001f);
    float cph = fminf(fmaxf(Y / r, -1.0f), 1.0f);
    float phw = acosf(cph);
    float thw = atan2f(X, Z);
    if (thw < 0.0f) thw += TWO_PI_F;

    float ix = thw * ((float)(WW - 1) / TWO_PI_F);   // in [0, 127)
    float iy = phw * ((float)(HH - 1) / PI_F);       // in [0, 63]

    float x0f = floorf(ix), y0f = floorf(iy);
    float wx1 = ix - x0f, wy1 = iy - y0f;
    float wx0 = 1.0f - wx1, wy0 = 1.0f - wy1;

    int x0 = min((int)x0f, WW - 1);       // x1 = x0+1 implicit; pad col covers x0==127
    int y0 = (int)y0f;
    int y1 = min(y0 + 1, HH - 1);         // wy1==0 when clamped

    float w00 = wx0 * wy0, w10 = wx1 * wy0, w01 = wx0 * wy1, w11 = wx1 * wy1;
    int packed = x0 | (y0 << 7) | (y1 << 13);

    // ---- phase 2: loop depths ----
    const float4* __restrict__ base =
        reinterpret_cast<const float4*>(g_featH) + (size_t)(1 - n) * HH * WW * 16;

    int out_base = ((n * DD * HH + h) << 7) + w;

    #pragma unroll 4
    for (int d = 0; d < DD; ++d) {
        int   pk  = __shfl_sync(0xffffffffu, packed, d);
        float b00 = __shfl_sync(0xffffffffu, w00, d);
        float b10 = __shfl_sync(0xffffffffu, w10, d);
        float b01 = __shfl_sync(0xffffffffu, w01, d);
        float b11 = __shfl_sync(0xffffffffu, w11, d);

        int bx0 = pk & 127;
        int by0 = (pk >> 7) & 63;
        int by1 = (pk >> 13) & 63;

        // span = columns (bx0, bx0+1) at row y: 32 float4; lane i takes #i
        float4 v0 = base[(((by0 << 7) + bx0) << 4) + lane];
        float4 v1 = base[(((by1 << 7) + bx0) << 4) + lane];

        const __half2* h0 = reinterpret_cast<const __half2*>(&v0);
        float2 c0 = __half22float2(h0[0]);
        float2 c1 = __half22float2(h0[1]);
        float2 c2 = __half22float2(h0[2]);
        float2 c3 = __half22float2(h0[3]);
        float dot0 = f0a.x * c0.x + f0a.y * c0.y + f0a.z * c1.x + f0a.w * c1.y
                   + f0b.x * c2.x + f0b.y * c2.y + f0b.z * c3.x + f0b.w * c3.y;

        const __half2* h1 = reinterpret_cast<const __half2*>(&v1);
        c0 = __half22float2(h1[0]);
        c1 = __half22float2(h1[1]);
        c2 = __half22float2(h1[2]);
        c3 = __half22float2(h1[3]);
        float dot1 = f0a.x * c0.x + f0a.y * c0.y + f0a.z * c1.x + f0a.w * c1.y
                   + f0b.x * c2.x + f0b.y * c2.y + f0b.z * c3.x + f0b.w * c3.y;

        float wsel0 = halfsel ? b10 : b00;
        float wsel1 = halfsel ? b11 : b01;
        float acc = wsel0 * dot0 + wsel1 * dot1;

        #pragma unroll
        for (int off = 16; off; off >>= 1)
            acc += __shfl_xor_sync(0xffffffffu, acc, off);

        if (lane == 0)
            out[out_base + ((d * HH) << 7)] = acc * 0.08838834764831844f; // 1/sqrt(128)
    }
}

extern "C" void kernel_launch(void* const* d_in, const int* in_sizes, int n_in,
                              void* d_out, int out_size) {
    const float* features = (const float*)d_in[0];
    const float* extr     = (const float*)d_in[1];
    const float* nearp    = (const float*)d_in[2];
    const float* farp     = (const float*)d_in[3];
    float* out = (float*)d_out;

    transpose_kernel<<<dim3(WW / 32, CH / 32, NV * HH), dim3(32, 8)>>>(
        features, extr, nearp, farp);
    corr_kernel<<<NV * HH * (WW / 16), 512>>>(out);
}

// round 6
// speedup vs baseline: 2.9803x; 1.2565x over previous
#include <cuda_runtime.h>
#include <cuda_fp16.h>
#include <math.h>

#define CH   128
#define HH   64
#define WW   128
#define DD   32
#define NV   2

#define TWO_PI_F 6.2831853071795864769f
#define PI_F     3.1415926535897932385f

// channel-last fp16 features: featH[v][h][w][c] (+ one zero column of pad)
__device__ __half g_featH[NV * HH * WW * CH + 2 * CH];     // 4 MB + pad
__device__ float  g_pose[2][12];
__device__ float  g_depth[2][DD];

// ---------------------------------------------------------------------------
// Transpose (v,c,h,w) -> (v,h,w,c) fp16. Block (0,0,0) also computes
// pose/depth tables. grid: (W/32, C/32, V*H), block (32, 8)
// ---------------------------------------------------------------------------
__global__ void transpose_kernel(const float* __restrict__ feat,
                                 const float* __restrict__ ex,
                                 const float* __restrict__ nearp,
                                 const float* __restrict__ farp) {
    __shared__ float tile[32][33];
    int v  = blockIdx.z >> 6;
    int h  = blockIdx.z & 63;
    int w0 = blockIdx.x << 5;
    int c0 = blockIdx.y << 5;
    int tx = threadIdx.x, ty = threadIdx.y;
    int lt = ty * 32 + tx;

    if (blockIdx.x == 0 && blockIdx.y == 0 && blockIdx.z == 0) {
        if (lt == 0) {
            float R0[3][3], R1[3][3], t0[3], t1[3];
            #pragma unroll
            for (int i = 0; i < 3; ++i) {
                #pragma unroll
                for (int j = 0; j < 3; ++j) {
                    R0[i][j] = ex[i * 4 + j];
                    R1[i][j] = ex[16 + i * 4 + j];
                }
                t0[i] = ex[i * 4 + 3];
                t1[i] = ex[16 + i * 4 + 3];
            }
            float Rp[3][3], tp[3];
            #pragma unroll
            for (int i = 0; i < 3; ++i) {
                #pragma unroll
                for (int j = 0; j < 3; ++j)
                    Rp[i][j] = R1[0][i] * R0[0][j] + R1[1][i] * R0[1][j] + R1[2][i] * R0[2][j];
                tp[i] = R1[0][i] * (t0[0] - t1[0]) + R1[1][i] * (t0[1] - t1[1])
                      + R1[2][i] * (t0[2] - t1[2]);
            }
            #pragma unroll
            for (int i = 0; i < 3; ++i) {
                #pragma unroll
                for (int j = 0; j < 3; ++j) {
                    g_pose[0][i * 4 + j] = Rp[i][j];
                    g_pose[1][i * 4 + j] = Rp[j][i];
                }
                g_pose[0][i * 4 + 3] = tp[i];
                g_pose[1][i * 4 + 3] = -(Rp[0][i] * tp[0] + Rp[1][i] * tp[1] + Rp[2][i] * tp[2]);
            }
        }
        if (lt >= 64 && lt < 64 + 2 * DD) {
            int t = lt - 64;
            int n = t >> 5;
            int d = t & (DD - 1);
            float mind = 1.0f / farp[n];
            float maxd = 1.0f / nearp[n];
            float lin  = (float)d * (1.0f / (float)(DD - 1));
            g_depth[n][d] = 1.0f / (mind + lin * (maxd - mind));
        }
    }

    #pragma unroll
    for (int i = 0; i < 32; i += 8)
        tile[ty + i][tx] = feat[(((v * CH) + (c0 + ty + i)) * HH + h) * WW + (w0 + tx)];
    __syncthreads();

    #pragma unroll
    for (int i = 0; i < 32; i += 8) {
        size_t idx = (size_t)(((v * HH + h) * WW) + (w0 + ty + i)) * CH + (c0 + tx);
        g_featH[idx] = __float2half_rn(tile[tx][ty + i]);
    }
}

// ---------------------------------------------------------------------------
// Main: block = (n, h, 16 adjacent w). 16 warps, 1 warp per pixel, 32 depths.
// Phase 1: lane d projects depth d -> {packed coords, 4 weights} into smem.
// Phase 2: per depth, 1 LDS.128+LDS (broadcast), 2 LDG.128 tap spans,
//          HFMA2 dot (both operands fp16), fp32 weighting + warp reduce.
// ---------------------------------------------------------------------------
__global__ void __launch_bounds__(512, 3) corr_kernel(float* __restrict__ out) {
    int bid = blockIdx.x;                 // 1024 blocks
    int wt = bid & 7;                     // 8 tiles of 16 pixels
    int h  = (bid >> 3) & (HH - 1);
    int n  = bid >> 9;

    __shared__ float s_pose[12];
    __shared__ float s_depth[DD];
    __shared__ float s_proj[16][DD][8];   // {packed, w00, w10, w01, w11, pad...}

    int tid  = threadIdx.x;
    int lane = tid & 31;
    int wid  = tid >> 5;

    if (tid < 12) s_pose[tid] = g_pose[n][tid];
    if (tid >= 32 && tid < 64) s_depth[tid - 32] = g_depth[n][tid - 32];
    __syncthreads();

    int w = wt * 16 + wid;
    int halfsel = lane >> 4;              // 0: x0 column, 1: x1 column
    int cidx = lane & 15;                 // channel group: 8*cidx .. +7

    // own-view fp16 feature column (8 channels per lane, as 4 x half2)
    const float4* __restrict__ fbase = reinterpret_cast<const float4*>(g_featH);
    float4 f0raw = fbase[(size_t)(((n * HH + h) * WW) + w) * 16 + cidx];
    const __half2* f0h = reinterpret_cast<const __half2*>(&f0raw);
    __half2 f0h0 = f0h[0], f0h1 = f0h[1], f0h2 = f0h[2], f0h3 = f0h[3];

    // ---- phase 1: per-lane projection for depth = lane ----
    {
        float theta = ((float)w + 0.5f) * (TWO_PI_F / (float)WW);
        float phi   = ((float)h + 0.5f) * (PI_F / (float)HH);
        float sth, cth, sphi, cphi;
        sincosf(theta, &sth, &cth);
        sincosf(phi, &sphi, &cphi);
        float dep = s_depth[lane];
        float px = dep * sphi * sth;
        float py = dep * cphi;
        float pz = dep * sphi * cth;

        float X = s_pose[0] * px + s_pose[1] * py + s_pose[2]  * pz + s_pose[3];
        float Y = s_pose[4] * px + s_pose[5] * py + s_pose[6]  * pz + s_pose[7];
        float Z = s_pose[8] * px + s_pose[9] * py + s_pose[10] * pz + s_pose[11];

        float r = fmaxf(sqrtf(X * X + Y * Y + Z * Z), 0.001f);
        float cph = fminf(fmaxf(Y / r, -1.0f), 1.0f);
        float phw = acosf(cph);
        float thw = atan2f(X, Z);
        if (thw < 0.0f) thw += TWO_PI_F;

        float ix = thw * ((float)(WW - 1) / TWO_PI_F);   // in [0, 127)
        float iy = phw * ((float)(HH - 1) / PI_F);       // in [0, 63]

        float x0f = floorf(ix), y0f = floorf(iy);
        float wx1 = ix - x0f, wy1 = iy - y0f;
        float wx0 = 1.0f - wx1, wy0 = 1.0f - wy1;

        int x0 = min((int)x0f, WW - 2);   // x1 = x0+1, always in-bounds
        int y0 = (int)y0f;
        int y1 = min(y0 + 1, HH - 1);     // wy1==0 when clamped

        int packed = x0 | (y0 << 7) | (y1 << 13);
        float* sp = s_proj[wid][lane];
        *reinterpret_cast<float4*>(sp) =
            make_float4(__int_as_float(packed), wx0 * wy0, wx1 * wy0, wx0 * wy1);
        sp[4] = wx1 * wy1;
    }
    __syncwarp();

    // ---- phase 2: loop depths ----
    const float4* __restrict__ base = fbase + (size_t)(1 - n) * HH * WW * 16;
    int out_base = ((n * DD * HH + h) << 7) + w;
    const __half2 hzero = __float2half2_rn(0.0f);

    #pragma unroll 4
    for (int d = 0; d < DD; ++d) {
        float4 pw = *reinterpret_cast<const float4*>(s_proj[wid][d]);   // LDS.128 broadcast
        float  w11 = s_proj[wid][d][4];
        int pk = __float_as_int(pw.x);

        int bx0 = pk & 127;
        int by0 = (pk >> 7) & 63;
        int by1 = (pk >> 13) & 63;

        // span = columns (x0, x0+1) at row y: 32 x float4; lane i takes #i
        float4 v0 = base[(((by0 << 7) + bx0) << 4) + lane];
        float4 v1 = base[(((by1 << 7) + bx0) << 4) + lane];

        const __half2* h0 = reinterpret_cast<const __half2*>(&v0);
        __half2 acc0 = __hmul2(f0h0, h0[0]);
        acc0 = __hfma2(f0h1, h0[1], acc0);
        acc0 = __hfma2(f0h2, h0[2], acc0);
        acc0 = __hfma2(f0h3, h0[3], acc0);

        const __half2* h1 = reinterpret_cast<const __half2*>(&v1);
        __half2 acc1 = __hmul2(f0h0, h1[0]);
        acc1 = __hfma2(f0h1, h1[1], acc1);
        acc1 = __hfma2(f0h2, h1[2], acc1);
        acc1 = __hfma2(f0h3, h1[3], acc1);

        float2 r0 = __half22float2(acc0);
        float2 r1 = __half22float2(acc1);

        float wsel0 = halfsel ? pw.z : pw.y;   // w10 : w00
        float wsel1 = halfsel ? w11  : pw.w;   // w11 : w01
        float acc = wsel0 * (r0.x + r0.y) + wsel1 * (r1.x + r1.y);

        #pragma unroll
        for (int off = 16; off; off >>= 1)
            acc += __shfl_xor_sync(0xffffffffu, acc, off);

        if (lane == 0)
            out[out_base + ((d * HH) << 7)] = acc * 0.08838834764831844f; // 1/sqrt(128)
    }
}

extern "C" void kernel_launch(void* const* d_in, const int* in_sizes, int n_in,
                              void* d_out, int out_size) {
    const float* features = (const float*)d_in[0];
    const float* extr     = (const float*)d_in[1];
    const float* nearp    = (const float*)d_in[2];
    const float* farp     = (const float*)d_in[3];
    float* out = (float*)d_out;

    transpose_kernel<<<dim3(WW / 32, CH / 32, NV * HH), dim3(32, 8)>>>(
        features, extr, nearp, farp);
    corr_kernel<<<NV * HH * (WW / 16), 512>>>(out);
}

// round 8
// speedup vs baseline: 3.1024x; 1.0410x over previous
#include <cuda_runtime.h>
#include <cuda_fp16.h>
#include <math.h>

#define CH   128
#define HH   64
#define WW   128
#define DD   32
#define NV   2

#define TWO_PI_F 6.2831853071795864769f
#define PI_F     3.1415926535897932385f

// channel-last fp16 features: featH[v][h][w][c] (+ one zero column of pad)
__device__ __half g_featH[NV * HH * WW * CH + 2 * CH];     // 4 MB + pad
__device__ float  g_pose[2][12];
__device__ float  g_depth[2][DD];

// ---------------------------------------------------------------------------
// Transpose (v,c,h,w) -> (v,h,w,c) fp16. Block (0,0,0) also computes
// pose/depth tables. grid: (W/32, C/32, V*H), block (32, 8)
// ---------------------------------------------------------------------------
__global__ void transpose_kernel(const float* __restrict__ feat,
                                 const float* __restrict__ ex,
                                 const float* __restrict__ nearp,
                                 const float* __restrict__ farp) {
    __shared__ float tile[32][33];
    int v  = blockIdx.z >> 6;
    int h  = blockIdx.z & 63;
    int w0 = blockIdx.x << 5;
    int c0 = blockIdx.y << 5;
    int tx = threadIdx.x, ty = threadIdx.y;
    int lt = ty * 32 + tx;

    if (blockIdx.x == 0 && blockIdx.y == 0 && blockIdx.z == 0) {
        if (lt == 0) {
            float R0[3][3], R1[3][3], t0[3], t1[3];
            #pragma unroll
            for (int i = 0; i < 3; ++i) {
                #pragma unroll
                for (int j = 0; j < 3; ++j) {
                    R0[i][j] = ex[i * 4 + j];
                    R1[i][j] = ex[16 + i * 4 + j];
                }
                t0[i] = ex[i * 4 + 3];
                t1[i] = ex[16 + i * 4 + 3];
            }
            float Rp[3][3], tp[3];
            #pragma unroll
            for (int i = 0; i < 3; ++i) {
                #pragma unroll
                for (int j = 0; j < 3; ++j)
                    Rp[i][j] = R1[0][i] * R0[0][j] + R1[1][i] * R0[1][j] + R1[2][i] * R0[2][j];
                tp[i] = R1[0][i] * (t0[0] - t1[0]) + R1[1][i] * (t0[1] - t1[1])
                      + R1[2][i] * (t0[2] - t1[2]);
            }
            #pragma unroll
            for (int i = 0; i < 3; ++i) {
                #pragma unroll
                for (int j = 0; j < 3; ++j) {
                    g_pose[0][i * 4 + j] = Rp[i][j];
                    g_pose[1][i * 4 + j] = Rp[j][i];
                }
                g_pose[0][i * 4 + 3] = tp[i];
                g_pose[1][i * 4 + 3] = -(Rp[0][i] * tp[0] + Rp[1][i] * tp[1] + Rp[2][i] * tp[2]);
            }
        }
        if (lt >= 64 && lt < 64 + 2 * DD) {
            int t = lt - 64;
            int n = t >> 5;
            int d = t & (DD - 1);
            float mind = 1.0f / farp[n];
            float maxd = 1.0f / nearp[n];
            float lin  = (float)d * (1.0f / (float)(DD - 1));
            g_depth[n][d] = 1.0f / (mind + lin * (maxd - mind));
        }
    }

    #pragma unroll
    for (int i = 0; i < 32; i += 8)
        tile[ty + i][tx] = feat[(((v * CH) + (c0 + ty + i)) * HH + h) * WW + (w0 + tx)];
    __syncthreads();

    #pragma unroll
    for (int i = 0; i < 32; i += 8) {
        size_t idx = (size_t)(((v * HH + h) * WW) + (w0 + ty + i)) * CH + (c0 + tx);
        g_featH[idx] = __float2half_rn(tile[tx][ty + i]);
    }
}

// ---------------------------------------------------------------------------
// Main: block = (n, h, 16 adjacent w). 16 warps, 1 warp per pixel, 32 depths.
// Phase 1: lane d projects depth d -> {packed coords, w00, w10, w01} (w11
//          implied: weights sum to 1 — no boundary zeroing possible here).
// Phase 2: per depth: LDS.128 broadcast; 4 x LDG.64 (lane-local channels of
//          all 4 taps); HFMA2 dot; fp32 weighting; 1 shfl; lanes 0-15 store
//          partial to smem.
// Phase 3: lane d sums its depth's 16 partials (conflict-free LDS.64), STG.
// ---------------------------------------------------------------------------
__global__ void __launch_bounds__(512, 3) corr_kernel(float* __restrict__ out) {
    int bid = blockIdx.x;                 // 1024 blocks
    int wt = bid & 7;                     // 8 tiles of 16 pixels
    int h  = (bid >> 3) & (HH - 1);
    int n  = bid >> 9;

    __shared__ float  s_pose[12];
    __shared__ float  s_depth[DD];
    __shared__ float4 s_proj[16][DD];     // {packed, w00, w10, w01}
    __shared__ float  s_part[16][DD][18]; // 16 partials + pad (stride 18)

    int tid  = threadIdx.x;
    int lane = tid & 31;
    int wid  = tid >> 5;

    if (tid < 12) s_pose[tid] = g_pose[n][tid];
    if (tid >= 32 && tid < 64) s_depth[tid - 32] = g_depth[n][tid - 32];
    __syncthreads();

    int w = wt * 16 + wid;

    // own-view fp16 feature: lane holds channels 4*lane .. 4*lane+3
    const uint2* __restrict__ f0p = reinterpret_cast<const uint2*>(
        g_featH + (size_t)(((n * HH + h) * WW) + w) * CH) + lane;
    uint2 f0q = *f0p;
    __half2 f0a = *reinterpret_cast<__half2*>(&f0q.x);
    __half2 f0b = *reinterpret_cast<__half2*>(&f0q.y);

    // ---- phase 1: per-lane projection for depth = lane ----
    {
        float theta = ((float)w + 0.5f) * (TWO_PI_F / (float)WW);
        float phi   = ((float)h + 0.5f) * (PI_F / (float)HH);
        float sth, cth, sphi, cphi;
        sincosf(theta, &sth, &cth);
        sincosf(phi, &sphi, &cphi);
        float dep = s_depth[lane];
        float px = dep * sphi * sth;
        float py = dep * cphi;
        float pz = dep * sphi * cth;

        float X = s_pose[0] * px + s_pose[1] * py + s_pose[2]  * pz + s_pose[3];
        float Y = s_pose[4] * px + s_pose[5] * py + s_pose[6]  * pz + s_pose[7];
        float Z = s_pose[8] * px + s_pose[9] * py + s_pose[10] * pz + s_pose[11];

        float r = fmaxf(sqrtf(X * X + Y * Y + Z * Z), 0.001f);
        float cph = fminf(fmaxf(Y / r, -1.0f), 1.0f);
        float phw = acosf(cph);
        float thw = atan2f(X, Z);
        if (thw < 0.0f) thw += TWO_PI_F;

        float ix = thw * ((float)(WW - 1) / TWO_PI_F);   // in [0, 127)
        float iy = phw * ((float)(HH - 1) / PI_F);       // in [0, 63]

        float x0f = floorf(ix), y0f = floorf(iy);
        float wx1 = ix - x0f, wy1 = iy - y0f;
        float wx0 = 1.0f - wx1, wy0 = 1.0f - wy1;

        int x0 = min((int)x0f, WW - 2);   // x1 = x0+1, always in-bounds
        int y0 = (int)y0f;
        int y1 = min(y0 + 1, HH - 1);     // wy1==0 when clamped

        int packed = x0 | (y0 << 7) | (y1 << 13);
        s_proj[wid][lane] =
            make_float4(__int_as_float(packed), wx0 * wy0, wx1 * wy0, wx0 * wy1);
    }
    __syncwarp();

    // ---- phase 2: loop depths ----
    const __half* __restrict__ hb = g_featH + (size_t)(1 - n) * HH * WW * CH;

    #pragma unroll 4
    for (int d = 0; d < DD; ++d) {
        float4 pw = s_proj[wid][d];                       // LDS.128 broadcast
        int pk = __float_as_int(pw.x);

        int bx0 = pk & 127;
        int by0 = (pk >> 7) & 63;
        int by1 = (pk >> 13) & 63;

        const uint2* r0p = reinterpret_cast<const uint2*>(hb + (((by0 << 7) + bx0) << 7)) + lane;
        const uint2* r1p = reinterpret_cast<const uint2*>(hb + (((by1 << 7) + bx0) << 7)) + lane;
        uint2 q00 = r0p[0];
        uint2 q10 = r0p[32];   // column x0+1, +256B immediate offset
        uint2 q01 = r1p[0];
        uint2 q11 = r1p[32];

        __half2 d00 = __hfma2(f0b, *reinterpret_cast<__half2*>(&q00.y),
                              __hmul2(f0a, *reinterpret_cast<__half2*>(&q00.x)));
        __half2 d10 = __hfma2(f0b, *reinterpret_cast<__half2*>(&q10.y),
                              __hmul2(f0a, *reinterpret_cast<__half2*>(&q10.x)));
        __half2 d01 = __hfma2(f0b, *reinterpret_cast<__half2*>(&q01.y),
                              __hmul2(f0a, *reinterpret_cast<__half2*>(&q01.x)));
        __half2 d11 = __hfma2(f0b, *reinterpret_cast<__half2*>(&q11.y),
                              __hmul2(f0a, *reinterpret_cast<__half2*>(&q11.x)));

        float2 e00 = __half22float2(d00);
        float2 e10 = __half22float2(d10);
        float2 e01 = __half22float2(d01);
        float2 e11 = __half22float2(d11);

        float w11v = 1.0f - pw.y - pw.z - pw.w;
        float ax = pw.y * e00.x + pw.z * e10.x + pw.w * e01.x + w11v * e11.x;
        float ay = pw.y * e00.y + pw.z * e10.y + pw.w * e01.y + w11v * e11.y;
        float acc = ax + ay;

        acc += __shfl_xor_sync(0xffffffffu, acc, 16);
        if (lane < 16) s_part[wid][d][lane] = acc;
    }
    __syncwarp();

    // ---- phase 3: lane d reduces its depth's 16 partials ----
    {
        const float* pp = s_part[wid][lane];
        float sum = 0.0f;
        #pragma unroll
        for (int k = 0; k < 16; ++k) sum += pp[k];
        out[(((n * DD + lane) * HH + h) << 7) + w] = sum * 0.08838834764831844f;
    }
}

extern "C" void kernel_launch(void* const* d_in, const int* in_sizes, int n_in,
                              void* d_out, int out_size) {
    const float* features = (const float*)d_in[0];
    const float* extr     = (const float*)d_in[1];
    const float* nearp    = (const float*)d_in[2];
    const float* farp     = (const float*)d_in[3];
    float* out = (float*)d_out;

    transpose_kernel<<<dim3(WW / 32, CH / 32, NV * HH), dim3(32, 8)>>>(
        features, extr, nearp, farp);
    corr_kernel<<<NV * HH * (WW / 16), 512>>>(out);
}

// round 9
// speedup vs baseline: 3.8450x; 1.2393x over previous
#include <cuda_runtime.h>
#include <cuda_fp16.h>
#include <math.h>

#define CH   128
#define HH   64
#define WW   128
#define DD   32
#define NV   2

#define TWO_PI_F 6.2831853071795864769f
#define PI_F     3.1415926535897932385f

// channel-last fp16 features: featH[v][h][w][c] (+ one zero column of pad)
__device__ __half g_featH[NV * HH * WW * CH + 2 * CH];     // 4 MB + pad
__device__ float  g_pose[2][12];
__device__ float  g_depth[2][DD];

// ---------------------------------------------------------------------------
// Transpose (v,c,h,w) -> (v,h,w,c) fp16. Block (0,0,0) also computes
// pose/depth tables. grid: (W/32, C/32, V*H), block (32, 8)
// ---------------------------------------------------------------------------
__global__ void transpose_kernel(const float* __restrict__ feat,
                                 const float* __restrict__ ex,
                                 const float* __restrict__ nearp,
                                 const float* __restrict__ farp) {
    __shared__ float tile[32][33];
    int v  = blockIdx.z >> 6;
    int h  = blockIdx.z & 63;
    int w0 = blockIdx.x << 5;
    int c0 = blockIdx.y << 5;
    int tx = threadIdx.x, ty = threadIdx.y;
    int lt = ty * 32 + tx;

    if (blockIdx.x == 0 && blockIdx.y == 0 && blockIdx.z == 0) {
        if (lt == 0) {
            float R0[3][3], R1[3][3], t0[3], t1[3];
            #pragma unroll
            for (int i = 0; i < 3; ++i) {
                #pragma unroll
                for (int j = 0; j < 3; ++j) {
                    R0[i][j] = ex[i * 4 + j];
                    R1[i][j] = ex[16 + i * 4 + j];
                }
                t0[i] = ex[i * 4 + 3];
                t1[i] = ex[16 + i * 4 + 3];
            }
            float Rp[3][3], tp[3];
            #pragma unroll
            for (int i = 0; i < 3; ++i) {
                #pragma unroll
                for (int j = 0; j < 3; ++j)
                    Rp[i][j] = R1[0][i] * R0[0][j] + R1[1][i] * R0[1][j] + R1[2][i] * R0[2][j];
                tp[i] = R1[0][i] * (t0[0] - t1[0]) + R1[1][i] * (t0[1] - t1[1])
                      + R1[2][i] * (t0[2] - t1[2]);
            }
            #pragma unroll
            for (int i = 0; i < 3; ++i) {
                #pragma unroll
                for (int j = 0; j < 3; ++j) {
                    g_pose[0][i * 4 + j] = Rp[i][j];
                    g_pose[1][i * 4 + j] = Rp[j][i];
                }
                g_pose[0][i * 4 + 3] = tp[i];
                g_pose[1][i * 4 + 3] = -(Rp[0][i] * tp[0] + Rp[1][i] * tp[1] + Rp[2][i] * tp[2]);
            }
        }
        if (lt >= 64 && lt < 64 + 2 * DD) {
            int t = lt - 64;
            int n = t >> 5;
            int d = t & (DD - 1);
            float mind = 1.0f / farp[n];
            float maxd = 1.0f / nearp[n];
            float lin  = (float)d * (1.0f / (float)(DD - 1));
            g_depth[n][d] = 1.0f / (mind + lin * (maxd - mind));
        }
    }

    #pragma unroll
    for (int i = 0; i < 32; i += 8)
        tile[ty + i][tx] = feat[(((v * CH) + (c0 + ty + i)) * HH + h) * WW + (w0 + tx)];
    __syncthreads();

    #pragma unroll
    for (int i = 0; i < 32; i += 8) {
        size_t idx = (size_t)(((v * HH + h) * WW) + (w0 + ty + i)) * CH + (c0 + tx);
        g_featH[idx] = __float2half_rn(tile[tx][ty + i]);
    }
}

__device__ __forceinline__ __half2 u2h2(unsigned int u) {
    return *reinterpret_cast<__half2*>(&u);
}

// ---------------------------------------------------------------------------
// Main: block = (n, h, 16 adjacent w). 16 warps, 1 warp per pixel, 32 depths.
// Phase 1: lane d projects depth d -> {lin0|lin1 packed, 4 fp16 weights}.
// Phase 2: per depth: LDS.128 broadcast; 4 x LDG.64; half2 bilinear combine
//          then half2 dot; 1 cvt; 1 shfl; lanes 0-15 store partial.
// Phase 3 (block-wide): thread t reduces (depth t>>4, pixel t&15); warp
//          writes two contiguous 64B output spans.
// ---------------------------------------------------------------------------
__global__ void __launch_bounds__(512, 3) corr_kernel(float* __restrict__ out) {
    int bid = blockIdx.x;                 // 1024 blocks
    int wt = bid & 7;                     // 8 tiles of 16 pixels
    int h  = (bid >> 3) & (HH - 1);
    int n  = bid >> 9;

    __shared__ float  s_pose[12];
    __shared__ float  s_depth[DD];
    __shared__ float4 s_proj[16][DD];     // {lin0|lin1<<13, h2(w00,w10), h2(w01,w11), -}
    __shared__ float  s_part[DD][16][19]; // stride 19: conflict-free r/w

    int tid  = threadIdx.x;
    int lane = tid & 31;
    int wid  = tid >> 5;

    if (tid < 12) s_pose[tid] = g_pose[n][tid];
    if (tid >= 32 && tid < 64) s_depth[tid - 32] = g_depth[n][tid - 32];
    __syncthreads();

    int w = wt * 16 + wid;

    // own-view fp16 feature: lane holds channels 4*lane .. 4*lane+3
    const uint2* __restrict__ f0p = reinterpret_cast<const uint2*>(
        g_featH + (size_t)(((n * HH + h) * WW) + w) * CH) + lane;
    uint2 f0q = *f0p;
    __half2 f0a = u2h2(f0q.x);
    __half2 f0b = u2h2(f0q.y);

    // ---- phase 1: per-lane projection for depth = lane ----
    {
        float theta = ((float)w + 0.5f) * (TWO_PI_F / (float)WW);
        float phi   = ((float)h + 0.5f) * (PI_F / (float)HH);
        float sth, cth, sphi, cphi;
        sincosf(theta, &sth, &cth);
        sincosf(phi, &sphi, &cphi);
        float dep = s_depth[lane];
        float px = dep * sphi * sth;
        float py = dep * cphi;
        float pz = dep * sphi * cth;

        float X = s_pose[0] * px + s_pose[1] * py + s_pose[2]  * pz + s_pose[3];
        float Y = s_pose[4] * px + s_pose[5] * py + s_pose[6]  * pz + s_pose[7];
        float Z = s_pose[8] * px + s_pose[9] * py + s_pose[10] * pz + s_pose[11];

        float r = fmaxf(sqrtf(X * X + Y * Y + Z * Z), 0.001f);
        float cph = fminf(fmaxf(Y / r, -1.0f), 1.0f);
        float phw = acosf(cph);
        float thw = atan2f(X, Z);
        if (thw < 0.0f) thw += TWO_PI_F;

        float ix = thw * ((float)(WW - 1) / TWO_PI_F);   // in [0, 127)
        float iy = phw * ((float)(HH - 1) / PI_F);       // in [0, 63]

        float x0f = floorf(ix), y0f = floorf(iy);
        float wx1 = ix - x0f, wy1 = iy - y0f;
        float wx0 = 1.0f - wx1, wy0 = 1.0f - wy1;

        int x0 = min((int)x0f, WW - 2);   // x1 = x0+1, always in-bounds
        int y0 = (int)y0f;
        int y1 = min(y0 + 1, HH - 1);     // wy1==0 when clamped

        int lin0 = (y0 << 7) + x0;        // 13 bits
        int lin1 = (y1 << 7) + x0;
        int packed = lin0 | (lin1 << 13);

        __half2 wA = __floats2half2_rn(wx0 * wy0, wx1 * wy0);   // (w00, w10)
        __half2 wB = __floats2half2_rn(wx0 * wy1, wx1 * wy1);   // (w01, w11)

        s_proj[wid][lane] = make_float4(
            __int_as_float(packed),
            __uint_as_float(*reinterpret_cast<unsigned int*>(&wA)),
            __uint_as_float(*reinterpret_cast<unsigned int*>(&wB)),
            0.0f);
    }
    __syncwarp();

    // ---- phase 2: loop depths ----
    const __half* __restrict__ hb = g_featH + (size_t)(1 - n) * HH * WW * CH;

    #pragma unroll 4
    for (int d = 0; d < DD; ++d) {
        float4 pw = s_proj[wid][d];                       // LDS.128 broadcast
        int pk = __float_as_int(pw.x);
        int lin0 = pk & 8191;
        int lin1 = (pk >> 13) & 8191;

        __half2 pA = u2h2(__float_as_uint(pw.y));
        __half2 pB = u2h2(__float_as_uint(pw.z));
        __half2 w00s = __low2half2(pA);
        __half2 w10s = __high2half2(pA);
        __half2 w01s = __low2half2(pB);
        __half2 w11s = __high2half2(pB);

        const uint2* r0p = reinterpret_cast<const uint2*>(hb + (lin0 << 7)) + lane;
        const uint2* r1p = reinterpret_cast<const uint2*>(hb + (lin1 << 7)) + lane;
        uint2 q00 = r0p[0];
        uint2 q10 = r0p[32];   // column x0+1, +256B immediate offset
        uint2 q01 = r1p[0];
        uint2 q11 = r1p[32];

        // bilinear combine in half2 (convex weights)
        __half2 ca = __hmul2(w00s, u2h2(q00.x));
        ca = __hfma2(w10s, u2h2(q10.x), ca);
        ca = __hfma2(w01s, u2h2(q01.x), ca);
        ca = __hfma2(w11s, u2h2(q11.x), ca);

        __half2 cb = __hmul2(w00s, u2h2(q00.y));
        cb = __hfma2(w10s, u2h2(q10.y), cb);
        cb = __hfma2(w01s, u2h2(q01.y), cb);
        cb = __hfma2(w11s, u2h2(q11.y), cb);

        // dot with own-view features
        __half2 ah = __hmul2(f0a, ca);
        ah = __hfma2(f0b, cb, ah);

        float2 e = __half22float2(ah);
        float acc = e.x + e.y;

        acc += __shfl_xor_sync(0xffffffffu, acc, 16);
        if (lane < 16) s_part[d][wid][lane] = acc;
    }
    __syncthreads();

    // ---- phase 3: thread t -> (depth t>>4, pixel t&15); coalesced writes ----
    {
        int d  = tid >> 4;
        int px = tid & 15;
        const float* pp = s_part[d][px];
        float sum = 0.0f;
        #pragma unroll
        for (int k = 0; k < 16; ++k) sum += pp[k];
        out[(((n * DD + d) * HH + h) << 7) + wt * 16 + px] =
            sum * 0.08838834764831844f;   // 1/sqrt(128)
    }
}

extern "C" void kernel_launch(void* const* d_in, const int* in_sizes, int n_in,
                              void* d_out, int out_size) {
    const float* features = (const float*)d_in[0];
    const float* extr     = (const float*)d_in[1];
    const float* nearp    = (const float*)d_in[2];
    const float* farp     = (const float*)d_in[3];
    float* out = (float*)d_out;

    transpose_kernel<<<dim3(WW / 32, CH / 32, NV * HH), dim3(32, 8)>>>(
        features, extr, nearp, farp);
    corr_kernel<<<NV * HH * (WW / 16), 512>>>(out);
}

// round 11
// speedup vs baseline: 4.3453x; 1.1301x over previous
#include <cuda_runtime.h>
#include <cuda_fp16.h>
#include <math.h>

#define CH   128
#define HH   64
#define WW   128
#define DD   32
#define NV   2

#define TWO_PI_F 6.2831853071795864769f
#define PI_F     3.1415926535897932385f

// channel-last fp16 features: featH[v][h][w][c] (+ pad)
__device__ __half g_featH[NV * HH * WW * CH + 2 * CH];     // 4 MB + pad
__device__ float  g_pose[2][12];
__device__ float  g_depth[2][DD];

// ---------------------------------------------------------------------------
// Transpose (v,c,h,w) -> (v,h,w,c) fp16, coalesced half2 stores.
// Block (0,0,0) also computes pose/depth tables.
// grid: (W/32, C/32, V*H), block (32, 8)
// ---------------------------------------------------------------------------
__global__ void transpose_kernel(const float* __restrict__ feat,
                                 const float* __restrict__ ex,
                                 const float* __restrict__ nearp,
                                 const float* __restrict__ farp) {
    __shared__ float tile[32][33];
    int v  = blockIdx.z >> 6;
    int h  = blockIdx.z & 63;
    int w0 = blockIdx.x << 5;
    int c0 = blockIdx.y << 5;
    int tx = threadIdx.x, ty = threadIdx.y;
    int lt = ty * 32 + tx;

    if (blockIdx.x == 0 && blockIdx.y == 0 && blockIdx.z == 0) {
        if (lt == 0) {
            float R0[3][3], R1[3][3], t0[3], t1[3];
            #pragma unroll
            for (int i = 0; i < 3; ++i) {
                #pragma unroll
                for (int j = 0; j < 3; ++j) {
                    R0[i][j] = ex[i * 4 + j];
                    R1[i][j] = ex[16 + i * 4 + j];
                }
                t0[i] = ex[i * 4 + 3];
                t1[i] = ex[16 + i * 4 + 3];
            }
            float Rp[3][3], tp[3];
            #pragma unroll
            for (int i = 0; i < 3; ++i) {
                #pragma unroll
                for (int j = 0; j < 3; ++j)
                    Rp[i][j] = R1[0][i] * R0[0][j] + R1[1][i] * R0[1][j] + R1[2][i] * R0[2][j];
                tp[i] = R1[0][i] * (t0[0] - t1[0]) + R1[1][i] * (t0[1] - t1[1])
                      + R1[2][i] * (t0[2] - t1[2]);
            }
            #pragma unroll
            for (int i = 0; i < 3; ++i) {
                #pragma unroll
                for (int j = 0; j < 3; ++j) {
                    g_pose[0][i * 4 + j] = Rp[i][j];
                    g_pose[1][i * 4 + j] = Rp[j][i];
                }
                g_pose[0][i * 4 + 3] = tp[i];
                g_pose[1][i * 4 + 3] = -(Rp[0][i] * tp[0] + Rp[1][i] * tp[1] + Rp[2][i] * tp[2]);
            }
        }
        if (lt >= 64 && lt < 64 + 2 * DD) {
            int t = lt - 64;
            int n = t >> 5;
            int d = t & (DD - 1);
            float mind = 1.0f / farp[n];
            float maxd = 1.0f / nearp[n];
            float lin  = (float)d * (1.0f / (float)(DD - 1));
            g_depth[n][d] = 1.0f / (mind + lin * (maxd - mind));
        }
    }

    #pragma unroll
    for (int i = 0; i < 32; i += 8)
        tile[ty + i][tx] = feat[(((v * CH) + (c0 + ty + i)) * HH + h) * WW + (w0 + tx)];
    __syncthreads();

    // coalesced half2 stores: 16 threads cover 32 channels for one w
    int cp = tx & 15;
    #pragma unroll
    for (int i = 0; i < 32; i += 16) {
        int wloc = ty + 8 * (tx >> 4) + i;        // 0..31
        __half2 hv = __floats2half2_rn(tile[2 * cp][wloc], tile[2 * cp + 1][wloc]);
        *reinterpret_cast<__half2*>(
            g_featH + (size_t)(((v * HH + h) * WW) + (w0 + wloc)) * CH + c0 + 2 * cp) = hv;
    }
}

__device__ __forceinline__ __half2 u2h2(unsigned int u) {
    return *reinterpret_cast<__half2*>(&u);
}

// ---------------------------------------------------------------------------
// Main: block = (n, h, 16 adjacent w). 16 warps; each warp = 2 pixels
// (16 lanes each, 8 channels/lane) x 16 depths.
// Phase 1: thread (px=tid&15, d=tid>>4) projects -> {lin0|lin1, fp16 weights}.
// Phase 2: per depth: dual-broadcast LDS.128; 4 x LDG.128 (each serving both
//          pixels); half2 bilinear combine + dot; 1 shfl(8); 8 partials.
// Phase 3: thread (d=tid>>4, px=tid&15) sums 8 partials, coalesced STG.
// ---------------------------------------------------------------------------
__global__ void __launch_bounds__(512, 3) corr_kernel(float* __restrict__ out) {
    int bid = blockIdx.x;                 // 1024 blocks
    int wt = bid & 7;                     // 8 tiles of 16 pixels
    int h  = (bid >> 3) & (HH - 1);
    int n  = bid >> 9;

    __shared__ float s_pose[12];
    __shared__ float s_depth[DD];
    __shared__ float s_projF[16 * 132];   // per px: 32 x float4 + 4-float pad
    __shared__ float s_part[DD][16][9];   // 8 partials + pad

    int tid  = threadIdx.x;
    int lane = tid & 31;
    int wid  = tid >> 5;

    if (tid < 12) s_pose[tid] = g_pose[n][tid];
    if (tid >= 32 && tid < 64) s_depth[tid - 32] = g_depth[n][tid - 32];
    __syncthreads();

    // ---- phase 1: one thread per (pixel, depth) ----
    {
        int px = tid & 15;
        int d  = tid >> 4;
        int w  = wt * 16 + px;

        float theta = ((float)w + 0.5f) * (TWO_PI_F / (float)WW);
        float phi   = ((float)h + 0.5f) * (PI_F / (float)HH);
        float sth, cth, sphi, cphi;
        sincosf(theta, &sth, &cth);
        sincosf(phi, &sphi, &cphi);
        float dep = s_depth[d];
        float px3 = dep * sphi * sth;
        float py3 = dep * cphi;
        float pz3 = dep * sphi * cth;

        float X = s_pose[0] * px3 + s_pose[1] * py3 + s_pose[2]  * pz3 + s_pose[3];
        float Y = s_pose[4] * px3 + s_pose[5] * py3 + s_pose[6]  * pz3 + s_pose[7];
        float Z = s_pose[8] * px3 + s_pose[9] * py3 + s_pose[10] * pz3 + s_pose[11];

        float r = fmaxf(sqrtf(X * X + Y * Y + Z * Z), 0.001f);
        float cph = fminf(fmaxf(Y / r, -1.0f), 1.0f);
        float phw = acosf(cph);
        float thw = atan2f(X, Z);
        if (thw < 0.0f) thw += TWO_PI_F;

        float ix = thw * ((float)(WW - 1) / TWO_PI_F);   // [0, 127)
        float iy = phw * ((float)(HH - 1) / PI_F);       // [0, 63]

        float x0f = floorf(ix), y0f = floorf(iy);
        float wx1 = ix - x0f, wy1 = iy - y0f;
        float wx0 = 1.0f - wx1, wy0 = 1.0f - wy1;

        int x0 = min((int)x0f, WW - 2);
        int y0 = (int)y0f;
        int y1 = min(y0 + 1, HH - 1);

        int lin0 = (y0 << 7) + x0;
        int lin1 = (y1 << 7) + x0;
        int packed = lin0 | (lin1 << 13);

        __half2 wA = __floats2half2_rn(wx0 * wy0, wx1 * wy0);   // (w00, w10)
        __half2 wB = __floats2half2_rn(wx0 * wy1, wx1 * wy1);   // (w01, w11)

        *reinterpret_cast<float4*>(&s_projF[px * 132 + d * 4]) = make_float4(
            __int_as_float(packed),
            __uint_as_float(*reinterpret_cast<unsigned int*>(&wA)),
            __uint_as_float(*reinterpret_cast<unsigned int*>(&wB)),
            0.0f);
    }
    __syncthreads();

    // ---- phase 2: 2 pixels per warp, 16 depths per warp ----
    int pxl = ((wid & 7) << 1) + (lane >> 4);    // this lane's pixel
    int dlo = (wid >> 3) << 4;                   // depth range base
    int cl  = lane & 15;                         // channel-group within pixel
    int w   = wt * 16 + pxl;

    const uint4* __restrict__ f0p = reinterpret_cast<const uint4*>(
        g_featH + (size_t)(((n * HH + h) * WW) + w) * CH) + cl;
    uint4 f0q = *f0p;
    __half2 f00 = u2h2(f0q.x), f01 = u2h2(f0q.y), f02 = u2h2(f0q.z), f03 = u2h2(f0q.w);

    const __half* __restrict__ hb = g_featH + (size_t)(1 - n) * HH * WW * CH;

    #pragma unroll 4
    for (int it = 0; it < 16; ++it) {
        int d = dlo + it;
        float4 pw = *reinterpret_cast<const float4*>(&s_projF[pxl * 132 + d * 4]);
        int pk = __float_as_int(pw.x);
        int lin0 = pk & 8191;
        int lin1 = (pk >> 13) & 8191;

        __half2 pA = u2h2(__float_as_uint(pw.y));
        __half2 pB = u2h2(__float_as_uint(pw.z));
        __half2 w00s = __low2half2(pA);
        __half2 w10s = __high2half2(pA);
        __half2 w01s = __low2half2(pB);
        __half2 w11s = __high2half2(pB);

        const uint4* r0 = reinterpret_cast<const uint4*>(hb + (lin0 << 7)) + cl;
        const uint4* r1 = reinterpret_cast<const uint4*>(hb + (lin1 << 7)) + cl;
        uint4 q00 = r0[0];
        uint4 q10 = r0[16];    // column x0+1: +256B immediate
        uint4 q01 = r1[0];
        uint4 q11 = r1[16];

        // bilinear combine in half2 (4 half2 channel slots)
        __half2 c0 = __hmul2(w00s, u2h2(q00.x));
        c0 = __hfma2(w10s, u2h2(q10.x), c0);
        c0 = __hfma2(w01s, u2h2(q01.x), c0);
        c0 = __hfma2(w11s, u2h2(q11.x), c0);

        __half2 c1 = __hmul2(w00s, u2h2(q00.y));
        c1 = __hfma2(w10s, u2h2(q10.y), c1);
        c1 = __hfma2(w01s, u2h2(q01.y), c1);
        c1 = __hfma2(w11s, u2h2(q11.y), c1);

        __half2 c2 = __hmul2(w00s, u2h2(q00.z));
        c2 = __hfma2(w10s, u2h2(q10.z), c2);
        c2 = __hfma2(w01s, u2h2(q01.z), c2);
        c2 = __hfma2(w11s, u2h2(q11.z), c2);

        __half2 c3 = __hmul2(w00s, u2h2(q00.w));
        c3 = __hfma2(w10s, u2h2(q10.w), c3);
        c3 = __hfma2(w01s, u2h2(q01.w), c3);
        c3 = __hfma2(w11s, u2h2(q11.w), c3);

        // dot with own-view features
        __half2 ah = __hmul2(f00, c0);
        ah = __hfma2(f01, c1, ah);
        ah = __hfma2(f02, c2, ah);
        ah = __hfma2(f03, c3, ah);

        float2 e = __half22float2(ah);
        float acc = e.x + e.y;

        acc += __shfl_xor_sync(0xffffffffu, acc, 8);
        if ((lane & 15) < 8) s_part[d][pxl][lane & 7] = acc;
    }
    __syncthreads();

    // ---- phase 3: thread (d, px) sums 8 partials; coalesced store ----
    {
        int d  = tid >> 4;
        int px = tid & 15;
        const float* pp = s_part[d][px];
        float sum = ((pp[0] + pp[1]) + (pp[2] + pp[3]))
                  + ((pp[4] + pp[5]) + (pp[6] + pp[7]));
        out[(((n * DD + d) * HH + h) << 7) + wt * 16 + px] =
            sum * 0.08838834764831844f;   // 1/sqrt(128)
    }
}

extern "C" void kernel_launch(void* const* d_in, const int* in_sizes, int n_in,
                              void* d_out, int out_size) {
    const float* features = (const float*)d_in[0];
    const float* extr     = (const float*)d_in[1];
    const float* nearp    = (const float*)d_in[2];
    const float* farp     = (const float*)d_in[3];
    float* out = (float*)d_out;

    transpose_kernel<<<dim3(WW / 32, CH / 32, NV * HH), dim3(32, 8)>>>(
        features, extr, nearp, farp);
    corr_kernel<<<NV * HH * (WW / 16), 512>>>(out);
}